// round 16
// baseline (speedup 1.0000x reference)
#include <cuda_runtime.h>
#include <cuda_bf16.h>
#include <math.h>
#include <stdint.h>

#define BB 4
#define TT 90
#define FR (BB*TT)          // 360 frames
#define HW 224
#define DIN 256

// ---- scratch (device globals; no allocation) ----
__device__ __align__(16) uint4 g_wBv[32*4*32];     // B frags: [kt2][j][lane], 64KB
__device__ float g_biasf[64];
__device__ __align__(16) float g_negA[256*16];     // -exp(A_log)
__device__ float g_pooled[FR*576];
__device__ float g_xm[FR*DIN];
__device__ float g_res[FR*DIN];
__device__ float g_u[FR*DIN];
__device__ float g_delta[FR*DIN];
__device__ __align__(16) float g_BC[FR*32];
__device__ float g_y[FR*DIN];

// ================= one-time prep =================
__global__ void wfold_kernel(const float* __restrict__ conv_w,
                             const float* __restrict__ conv_b,
                             const float* __restrict__ gma,
                             const float* __restrict__ bta,
                             const float* __restrict__ mean,
                             const float* __restrict__ var,
                             const float* __restrict__ A_log)
{
    int idx = blockIdx.x * 256 + threadIdx.x;
    if (idx < 64) {
        float inv = gma[idx] * rsqrtf(var[idx] + 1e-5f);
        g_biasf[idx] = (conv_b[idx] - mean[idx]) * inv + bta[idx];
    }
    if (idx < 4096) g_negA[idx] = -expf(A_log[idx]);
    if (idx >= 32*4*32) return;
    int kt2  = idx >> 7;
    int j    = (idx >> 5) & 3;
    int lane = idx & 31;
    uint32_t comp[4];
    #pragma unroll
    for (int c = 0; c < 4; c++) {
        int nt = 2*j + (c >> 1); int h = c & 1;
        int n = nt*8 + (lane >> 2);
        int kbase = kt2*16 + h*8 + (lane & 3)*2;
        float inv = gma[n] * rsqrtf(var[n] + 1e-5f);
        float v[2];
        #pragma unroll
        for (int e = 0; e < 2; e++) {
            int k = kbase + e;
            int s = k >> 3, kx = k & 7;
            float val = 0.f;
            if (s < 63 && kx < 7) {
                int p = s / 7, ky = s % 7;
                int kt = p / 3, cc = p % 3;
                val = conv_w[(n*3 + cc)*147 + kt*49 + ky*7 + kx] * inv;
            }
            v[e] = val;
        }
        __nv_bfloat162 pk = __floats2bfloat162_rn(v[0], v[1]);
        comp[c] = *(uint32_t*)&pk;
    }
    g_wBv[idx] = make_uint4(comp[0], comp[1], comp[2], comp[3]);
}

__global__ void zero_pooled_kernel(int off) {
    int i = off + blockIdx.x * 256 + threadIdx.x;
    if (i < FR*576) g_pooled[i] = 0.f;
}

// ================= conv via mma.sync (HMMA) — FROZEN (R10 core + R15 epi) ==
#define SIN_U32ROW 116
#define SMEM_POOL_OFF 45936
#define CONV_SMEM (SMEM_POOL_OFF + 576*4)   // 48,240 B -> 4 CTAs/SM

__device__ __forceinline__ void mma16816(float* c, const uint32_t* a,
                                         uint32_t b0, uint32_t b1) {
    asm volatile(
        "mma.sync.aligned.m16n8k16.row.col.f32.bf16.bf16.f32 "
        "{%0,%1,%2,%3}, {%4,%5,%6,%7}, {%8,%9}, {%0,%1,%2,%3};"
        : "+f"(c[0]), "+f"(c[1]), "+f"(c[2]), "+f"(c[3])
        : "r"(a[0]), "r"(a[1]), "r"(a[2]), "r"(a[3]), "r"(b0), "r"(b1));
}

__device__ __forceinline__ float gelu_exact(float v) {
    return 0.5f * v * (1.0f + erff(v * 0.70710678118654752f));
}

__global__ __launch_bounds__(256, 4)
void conv_mma_kernel(const float* __restrict__ rgb)
{
    extern __shared__ char sm[];
    const uint32_t* in32 = (const uint32_t*)sm;
    float* s_pool        = (float*)(sm + SMEM_POOL_OFF);

    int blk = blockIdx.x;
    int yp = blk % 28; int frame = blk / 28;
    int t = frame % TT; int b = frame / TT;
    int tid = threadIdx.x;
    int w = tid >> 5; int lane = tid & 31;
    int g = lane >> 2; int q = lane & 3;
    int wm = w & 3;    int nh = w >> 2;

    for (int i = tid; i < 576; i += 256) s_pool[i] = 0.f;

    int rowbase = 8*yp - 3;
    for (int r = w; r < 99; r += 8) {
        int pIdx = r / 11, iy = r % 11;
        int tin = t + pIdx/3 - 1; int c = pIdx % 3;
        int grow = rowbase + iy;
        bool rv = (tin >= 0) && (tin < TT) && (grow >= 0) && (grow < HW);
        const float* src = rgb + (((size_t)(b*TT + tin)*3 + c)*HW + grow)*HW;
        uint32_t* dst = (uint32_t*)sm + (pIdx*11 + iy)*SIN_U32ROW;
        #pragma unroll
        for (int it = 0; it < 4; it++) {
            int x2 = lane + it*32;
            if (x2 < 114) {
                int c0 = 2*x2 - 3, c1 = c0 + 1;
                float v0 = (rv && c0 >= 0 && c0 < HW) ? src[c0] : 0.f;
                float v1 = (rv && c1 >= 0 && c1 < HW) ? src[c1] : 0.f;
                __nv_bfloat162 pk = __floats2bfloat162_rn(v0, v1);
                dst[x2] = *(uint32_t*)&pk;
            }
        }
    }
    __syncthreads();

    int x_lo = wm*16 + g;
    int x_hi = x_lo + 8; if (x_hi > 55) x_hi = 55;
    int blo = 2*x_lo + q;
    int bhi = 2*x_hi + q;

    float acc[2][4][4];
    #pragma unroll
    for (int y = 0; y < 2; y++)
        #pragma unroll
        for (int nt = 0; nt < 4; nt++)
            #pragma unroll
            for (int e = 0; e < 4; e++) acc[y][nt][e] = 0.f;

    const uint4* btab = g_wBv + nh*64 + lane;

    #pragma unroll
    for (int kt2 = 0; kt2 < 32; kt2++) {
        const int s0 = 2*kt2, s1 = s0 + 1;
        const int p0 = s0 / 7, ky0 = s0 - 7*p0;
        const int p1 = s1 / 7, ky1 = s1 - 7*p1;
        const int o0 = (p0*11 + ky0)*SIN_U32ROW;
        const int o1 = (s1 == 63) ? o0 : (p1*11 + ky1)*SIN_U32ROW;

        uint4 B0 = __ldg(btab + kt2*128);
        uint4 B1 = __ldg(btab + kt2*128 + 32);

        uint32_t a0[4], a1[4];
        a0[0] = in32[o0 + blo];        a0[1] = in32[o0 + bhi];
        a0[2] = in32[o1 + blo];        a0[3] = in32[o1 + bhi];
        a1[0] = in32[o0 + 464 + blo];  a1[1] = in32[o0 + 464 + bhi];
        a1[2] = in32[o1 + 464 + blo];  a1[3] = in32[o1 + 464 + bhi];

        mma16816(acc[0][0], a0, B0.x, B0.y);  mma16816(acc[1][0], a1, B0.x, B0.y);
        mma16816(acc[0][1], a0, B0.z, B0.w);  mma16816(acc[1][1], a1, B0.z, B0.w);
        mma16816(acc[0][2], a0, B1.x, B1.y);  mma16816(acc[1][2], a1, B1.x, B1.y);
        mma16816(acc[0][3], a0, B1.z, B1.w);  mma16816(acc[1][3], a1, B1.z, B1.w);
    }

    // ---- epilogue: bias + exact GELU + pool bins (floor 18/19/19) ----
    const float i18 = 1.f/18.f, i19 = 1.f/19.f;
    const int rowg0 = 2*yp, rowg1 = 2*yp + 1;
    const float rw0 = (rowg0 < 18) ? i18 : i19;
    const float rw1 = (rowg1 < 18) ? i18 : i19;
    const int roff0 = (rowg0 < 18) ? 0 : ((rowg0 < 37) ? 3 : 6);
    const int roff1 = (rowg1 < 18) ? 0 : ((rowg1 < 37) ? 3 : 6);
    const bool ymerge = (roff0 == roff1);

    const int x0 = wm*16 + g;
    const int x1 = x0 + 8;
    const bool v1 = (x1 < 56);
    const int xb0 = (x0 < 18) ? 0 : ((x0 < 37) ? 1 : 2);
    const int xb1 = (x1 < 18) ? 0 : ((x1 < 37) ? 1 : 2);
    const float cw0 = (x0 < 18) ? i18 : i19;
    const float cw1 = (x1 < 18) ? i18 : i19;
    const bool xmerge = v1 && (xb0 == xb1);

    #pragma unroll
    for (int nt = 0; nt < 4; nt++) {
        int ch0 = (nh*4 + nt)*8 + q*2;
        #pragma unroll
        for (int e = 0; e < 2; e++) {
            float bv = __ldg(g_biasf + ch0 + e);
            float g00 = gelu_exact(acc[0][nt][e] + bv);
            float g10 = gelu_exact(acc[1][nt][e] + bv);
            float* base = &s_pool[(ch0 + e)*9];
            if (v1) {
                float g01 = gelu_exact(acc[0][nt][2 + e] + bv);
                float g11 = gelu_exact(acc[1][nt][2 + e] + bv);
                if (ymerge) {
                    if (xmerge) {
                        atomicAdd(base + roff0 + xb0,
                                  ((g00 + g01)*rw0 + (g10 + g11)*rw1)*cw0);
                    } else {
                        atomicAdd(base + roff0 + xb0, (g00*rw0 + g10*rw1)*cw0);
                        atomicAdd(base + roff0 + xb1, (g01*rw0 + g11*rw1)*cw1);
                    }
                } else {
                    atomicAdd(base + roff0 + xb0, g00*rw0*cw0);
                    atomicAdd(base + roff1 + xb0, g10*rw1*cw0);
                    atomicAdd(base + roff0 + xb1, g01*rw0*cw1);
                    atomicAdd(base + roff1 + xb1, g11*rw1*cw1);
                }
            } else {
                if (ymerge) {
                    atomicAdd(base + roff0 + xb0, (g00*rw0 + g10*rw1)*cw0);
                } else {
                    atomicAdd(base + roff0 + xb0, g00*rw0*cw0);
                    atomicAdd(base + roff1 + xb0, g10*rw1*cw0);
                }
            }
        }
    }
    __syncthreads();
    int base = frame*576;
    for (int i = tid; i < 576; i += 256) atomicAdd(&g_pooled[base + i], s_pool[i]);
}

// ================= Mamba chain =================
// proj+in_proj batched over 4 positions per block (weights read once per block)
__global__ void proj_inproj_kernel(const float* __restrict__ proj_w,
                                   const float* __restrict__ proj_b,
                                   const float* __restrict__ in_w)
{
    __shared__ __align__(16) float s_p[4][576];
    __shared__ __align__(16) float s_x[4][128];
    int pos0 = blockIdx.x * 4;
    int tid = threadIdx.x;           // 256
    int w = tid >> 5, lane = tid & 31;
    for (int i = tid; i < 4*576; i += 256)
        ((float*)s_p)[i] = g_pooled[pos0*576 + i];
    __syncthreads();

    // phase 1: 128 rows of proj (K=576), each row dotted with 4 positions
    #pragma unroll
    for (int rr = 0; rr < 16; rr++) {
        int row = w*16 + rr;
        const float4* w4 = (const float4*)(proj_w + row*576);
        float a0 = 0.f, a1 = 0.f, a2 = 0.f, a3 = 0.f;
        #pragma unroll
        for (int i = 0; i < 4; i++) {
            float4 wv = __ldg(w4 + lane + 32*i);
            const float4 x0 = ((const float4*)s_p[0])[lane + 32*i];
            const float4 x1 = ((const float4*)s_p[1])[lane + 32*i];
            const float4 x2 = ((const float4*)s_p[2])[lane + 32*i];
            const float4 x3 = ((const float4*)s_p[3])[lane + 32*i];
            a0 += wv.x*x0.x + wv.y*x0.y + wv.z*x0.z + wv.w*x0.w;
            a1 += wv.x*x1.x + wv.y*x1.y + wv.z*x1.z + wv.w*x1.w;
            a2 += wv.x*x2.x + wv.y*x2.y + wv.z*x2.z + wv.w*x2.w;
            a3 += wv.x*x3.x + wv.y*x3.y + wv.z*x3.z + wv.w*x3.w;
        }
        if (lane < 16) {
            float4 wv = __ldg(w4 + 128 + lane);
            const float4 x0 = ((const float4*)s_p[0])[128 + lane];
            const float4 x1 = ((const float4*)s_p[1])[128 + lane];
            const float4 x2 = ((const float4*)s_p[2])[128 + lane];
            const float4 x3 = ((const float4*)s_p[3])[128 + lane];
            a0 += wv.x*x0.x + wv.y*x0.y + wv.z*x0.z + wv.w*x0.w;
            a1 += wv.x*x1.x + wv.y*x1.y + wv.z*x1.z + wv.w*x1.w;
            a2 += wv.x*x2.x + wv.y*x2.y + wv.z*x2.z + wv.w*x2.w;
            a3 += wv.x*x3.x + wv.y*x3.y + wv.z*x3.z + wv.w*x3.w;
        }
        #pragma unroll
        for (int o = 16; o > 0; o >>= 1) {
            a0 += __shfl_xor_sync(0xffffffffu, a0, o);
            a1 += __shfl_xor_sync(0xffffffffu, a1, o);
            a2 += __shfl_xor_sync(0xffffffffu, a2, o);
            a3 += __shfl_xor_sync(0xffffffffu, a3, o);
        }
        if (lane == 0) {
            float pb = __ldg(proj_b + row);
            s_x[0][row] = a0 + pb;  s_x[1][row] = a1 + pb;
            s_x[2][row] = a2 + pb;  s_x[3][row] = a3 + pb;
        }
    }
    __syncthreads();

    // phase 2: 512 rows of in_proj (K=128 = 1 float4/lane), 4 positions each
    #pragma unroll
    for (int rr = 0; rr < 64; rr++) {
        int row = w*64 + rr;
        float4 wv = __ldg((const float4*)(in_w + row*128) + lane);
        float4 x0 = ((const float4*)s_x[0])[lane];
        float4 x1 = ((const float4*)s_x[1])[lane];
        float4 x2 = ((const float4*)s_x[2])[lane];
        float4 x3 = ((const float4*)s_x[3])[lane];
        float a0 = wv.x*x0.x + wv.y*x0.y + wv.z*x0.z + wv.w*x0.w;
        float a1 = wv.x*x1.x + wv.y*x1.y + wv.z*x1.z + wv.w*x1.w;
        float a2 = wv.x*x2.x + wv.y*x2.y + wv.z*x2.z + wv.w*x2.w;
        float a3 = wv.x*x3.x + wv.y*x3.y + wv.z*x3.z + wv.w*x3.w;
        #pragma unroll
        for (int o = 16; o > 0; o >>= 1) {
            a0 += __shfl_xor_sync(0xffffffffu, a0, o);
            a1 += __shfl_xor_sync(0xffffffffu, a1, o);
            a2 += __shfl_xor_sync(0xffffffffu, a2, o);
            a3 += __shfl_xor_sync(0xffffffffu, a3, o);
        }
        if (lane == 0) {
            float av[4] = {a0, a1, a2, a3};
            #pragma unroll
            for (int p = 0; p < 4; p++) {
                if (row < 256) g_xm[(pos0 + p)*256 + row] = av[p];
                else           g_res[(pos0 + p)*256 + (row - 256)] = av[p];
            }
        }
    }
}

__global__ void conv1d_xproj_kernel(const float* __restrict__ cw,
                                    const float* __restrict__ cb,
                                    const float* __restrict__ xw,
                                    const float* __restrict__ dtw,
                                    const float* __restrict__ dtb)
{
    __shared__ __align__(16) float s_u[256];
    __shared__ float s_xd[40];
    int pos = blockIdx.x; int b = pos / TT; int l = pos % TT;
    int d = threadIdx.x;             // 256
    int w = d >> 5, lane = d & 31;

    float xc = cb[d];
    #pragma unroll
    for (int k = 0; k < 4; k++) {
        int li = l - 3 + k;
        if (li >= 0) xc = fmaf(g_xm[(b*TT + li)*256 + d], cw[d*4 + k], xc);
    }
    float u = xc / (1.f + expf(-xc));
    s_u[d] = u;
    g_u[pos*256 + d] = u;
    __syncthreads();

    #pragma unroll
    for (int rr = 0; rr < 5; rr++) {
        int row = w*5 + rr;
        float4 w0 = __ldg((const float4*)(xw + row*256) + lane);
        float4 w1 = __ldg((const float4*)(xw + row*256) + 32 + lane);
        float4 x0 = *((const float4*)s_u + lane);
        float4 x1 = *((const float4*)s_u + 32 + lane);
        float a = w0.x*x0.x + w0.y*x0.y + w0.z*x0.z + w0.w*x0.w
                + w1.x*x1.x + w1.y*x1.y + w1.z*x1.z + w1.w*x1.w;
        #pragma unroll
        for (int o = 16; o > 0; o >>= 1) a += __shfl_xor_sync(0xffffffffu, a, o);
        if (lane == 0) s_xd[row] = a;
    }
    __syncthreads();

    float dr = dtb[d];
    #pragma unroll
    for (int k = 0; k < 8; k++) dr = fmaf(dtw[d*8 + k], s_xd[k], dr);
    float delta = (dr > 20.f) ? dr : log1pf(expf(dr));
    g_delta[pos*256 + d] = delta;
    if (d < 32) g_BC[pos*32 + d] = s_xd[8 + d];
}

// scan: thread = (b, d, n-quad). 4096 threads = 32 blocks x 128.
// h recurrences independent across n; y reduced over the 4-thread quad.
__global__ void scan_kernel(const float* __restrict__ Dp)
{
    int gidx = blockIdx.x * 128 + threadIdx.x;
    int b  = gidx >> 10;
    int rem = gidx & 1023;
    int d  = rem >> 2;
    int ng = rem & 3;

    float A[4], h[4];
    {
        float4 v = __ldg((const float4*)(g_negA + d*16) + ng);
        A[0] = v.x; A[1] = v.y; A[2] = v.z; A[3] = v.w;
    }
    #pragma unroll
    for (int n = 0; n < 4; n++) h[n] = 0.f;
    float Dd = __ldg(Dp + d);

    for (int l = 0; l < TT; l++) {
        int pos = b*TT + l;
        float delta = g_delta[pos*256 + d];
        float u     = g_u[pos*256 + d];
        const float4* BC4 = (const float4*)(g_BC + pos*32);
        float4 Bv = __ldg(BC4 + ng);
        float4 Cv = __ldg(BC4 + 4 + ng);
        float du = delta * u;
        const float* Bf = (const float*)&Bv;
        const float* Cf = (const float*)&Cv;
        float y = 0.f;
        #pragma unroll
        for (int n = 0; n < 4; n++) {
            float dA = expf(delta * A[n]);
            h[n] = fmaf(dA, h[n], du * Bf[n]);
            y = fmaf(h[n], Cf[n], y);
        }
        y += __shfl_xor_sync(0xffffffffu, y, 1);
        y += __shfl_xor_sync(0xffffffffu, y, 2);
        if (ng == 0) {
            float res = g_res[pos*256 + d];
            y = fmaf(u, Dd, y);
            y *= res / (1.f + expf(-res));
            g_y[pos*256 + d] = y;
        }
    }
}

// out projection batched over 4 positions per block
__global__ void outproj_kernel(const float* __restrict__ ow,
                               float* __restrict__ out)
{
    __shared__ __align__(16) float s_y[4][256];
    int pos0 = blockIdx.x * 4;
    int tid = threadIdx.x;           // 256
    int w = tid >> 5, lane = tid & 31;
    #pragma unroll
    for (int p = 0; p < 4; p++) s_y[p][tid] = g_y[(pos0 + p)*256 + tid];
    __syncthreads();
    #pragma unroll
    for (int rr = 0; rr < 16; rr++) {
        int row = w*16 + rr;
        float4 w0 = __ldg((const float4*)(ow + row*256) + lane);
        float4 w1 = __ldg((const float4*)(ow + row*256) + 32 + lane);
        float a[4];
        #pragma unroll
        for (int p = 0; p < 4; p++) {
            float4 y0 = ((const float4*)s_y[p])[lane];
            float4 y1 = ((const float4*)s_y[p])[32 + lane];
            a[p] = w0.x*y0.x + w0.y*y0.y + w0.z*y0.z + w0.w*y0.w
                 + w1.x*y1.x + w1.y*y1.y + w1.z*y1.z + w1.w*y1.w;
        }
        #pragma unroll
        for (int o = 16; o > 0; o >>= 1) {
            a[0] += __shfl_xor_sync(0xffffffffu, a[0], o);
            a[1] += __shfl_xor_sync(0xffffffffu, a[1], o);
            a[2] += __shfl_xor_sync(0xffffffffu, a[2], o);
            a[3] += __shfl_xor_sync(0xffffffffu, a[3], o);
        }
        if (lane == 0) {
            #pragma unroll
            for (int p = 0; p < 4; p++) out[(pos0 + p)*128 + row] = a[p];
        }
    }
}

// ============================================================
extern "C" void kernel_launch(void* const* d_in, const int* in_sizes, int n_in,
                              void* d_out, int out_size)
{
    (void)in_sizes; (void)n_in; (void)out_size;
    const float* rgb     = (const float*)d_in[0];
    const float* conv_w  = (const float*)d_in[1];
    const float* conv_b  = (const float*)d_in[2];
    const float* bn_g    = (const float*)d_in[3];
    const float* bn_b    = (const float*)d_in[4];
    const float* bn_m    = (const float*)d_in[5];
    const float* bn_v    = (const float*)d_in[6];
    const float* proj_w  = (const float*)d_in[7];
    const float* proj_b  = (const float*)d_in[8];
    const float* m_in_w  = (const float*)d_in[9];
    const float* m_cw    = (const float*)d_in[10];
    const float* m_cb    = (const float*)d_in[11];
    const float* m_xw    = (const float*)d_in[12];
    const float* m_dtw   = (const float*)d_in[13];
    const float* m_dtb   = (const float*)d_in[14];
    const float* m_Alog  = (const float*)d_in[15];
    const float* m_D     = (const float*)d_in[16];
    const float* m_ow    = (const float*)d_in[17];
    float* out = (float*)d_out;

    cudaFuncSetAttribute(conv_mma_kernel,
                         cudaFuncAttributeMaxDynamicSharedMemorySize, CONV_SMEM);

    // wfold + 2 zeros position conv at ncu launch index 5
    wfold_kernel<<<(32*4*32 + 255)/256, 256>>>(conv_w, conv_b, bn_g, bn_b,
                                               bn_m, bn_v, m_Alog);
    const int H = (FR*576) / 2;
    zero_pooled_kernel<<<(H + 255)/256, 256>>>(0);
    zero_pooled_kernel<<<(H + 255)/256, 256>>>(H);

    conv_mma_kernel<<<FR*28, 256, CONV_SMEM>>>(rgb);

    proj_inproj_kernel<<<FR/4, 256>>>(proj_w, proj_b, m_in_w);
    conv1d_xproj_kernel<<<FR, 256>>>(m_cw, m_cb, m_xw, m_dtw, m_dtb);
    scan_kernel<<<32, 128>>>(m_D);
    outproj_kernel<<<FR/4, 256>>>(m_ow, out);
}

// round 17
// speedup vs baseline: 1.0566x; 1.0566x over previous
#include <cuda_runtime.h>
#include <cuda_bf16.h>
#include <math.h>
#include <stdint.h>

#define BB 4
#define TT 90
#define FR (BB*TT)          // 360 frames
#define HW 224
#define DIN 256

// ---- scratch (device globals; no allocation) ----
__device__ __align__(16) uint4 g_wBv[32*4*32];     // B frags: [kt2][j][lane], 64KB
__device__ float g_biasf[64];
__device__ __align__(16) float g_negA[256*16];     // -exp(A_log)
__device__ float g_pooled[FR*576];
__device__ float g_xm[FR*DIN];
__device__ float g_res[FR*DIN];
__device__ float g_u[FR*DIN];
__device__ float g_delta[FR*DIN];
__device__ __align__(16) float g_BC[FR*32];
__device__ float g_y[FR*DIN];

// ================= one-time prep =================
__global__ void wfold_kernel(const float* __restrict__ conv_w,
                             const float* __restrict__ conv_b,
                             const float* __restrict__ gma,
                             const float* __restrict__ bta,
                             const float* __restrict__ mean,
                             const float* __restrict__ var,
                             const float* __restrict__ A_log)
{
    int idx = blockIdx.x * 256 + threadIdx.x;
    if (idx < 64) {
        float inv = gma[idx] * rsqrtf(var[idx] + 1e-5f);
        g_biasf[idx] = (conv_b[idx] - mean[idx]) * inv + bta[idx];
    }
    if (idx < 4096) g_negA[idx] = -expf(A_log[idx]);
    if (idx >= 32*4*32) return;
    int kt2  = idx >> 7;
    int j    = (idx >> 5) & 3;
    int lane = idx & 31;
    uint32_t comp[4];
    #pragma unroll
    for (int c = 0; c < 4; c++) {
        int nt = 2*j + (c >> 1); int h = c & 1;
        int n = nt*8 + (lane >> 2);
        int kbase = kt2*16 + h*8 + (lane & 3)*2;
        float inv = gma[n] * rsqrtf(var[n] + 1e-5f);
        float v[2];
        #pragma unroll
        for (int e = 0; e < 2; e++) {
            int k = kbase + e;
            int s = k >> 3, kx = k & 7;
            float val = 0.f;
            if (s < 63 && kx < 7) {
                int p = s / 7, ky = s % 7;
                int kt = p / 3, cc = p % 3;
                val = conv_w[(n*3 + cc)*147 + kt*49 + ky*7 + kx] * inv;
            }
            v[e] = val;
        }
        __nv_bfloat162 pk = __floats2bfloat162_rn(v[0], v[1]);
        comp[c] = *(uint32_t*)&pk;
    }
    g_wBv[idx] = make_uint4(comp[0], comp[1], comp[2], comp[3]);
}

__global__ void zero_pooled_kernel(int off) {
    int i = off + blockIdx.x * 256 + threadIdx.x;
    if (i < FR*576) g_pooled[i] = 0.f;
}

// ================= conv via mma.sync (HMMA) — FROZEN =================
#define SIN_U32ROW 116
#define SMEM_POOL_OFF 45936
#define CONV_SMEM (SMEM_POOL_OFF + 576*4)   // 48,240 B -> 4 CTAs/SM

__device__ __forceinline__ void mma16816(float* c, const uint32_t* a,
                                         uint32_t b0, uint32_t b1) {
    asm volatile(
        "mma.sync.aligned.m16n8k16.row.col.f32.bf16.bf16.f32 "
        "{%0,%1,%2,%3}, {%4,%5,%6,%7}, {%8,%9}, {%0,%1,%2,%3};"
        : "+f"(c[0]), "+f"(c[1]), "+f"(c[2]), "+f"(c[3])
        : "r"(a[0]), "r"(a[1]), "r"(a[2]), "r"(a[3]), "r"(b0), "r"(b1));
}

__device__ __forceinline__ float gelu_exact(float v) {
    return 0.5f * v * (1.0f + erff(v * 0.70710678118654752f));
}

__global__ __launch_bounds__(256, 4)
void conv_mma_kernel(const float* __restrict__ rgb)
{
    extern __shared__ char sm[];
    const uint32_t* in32 = (const uint32_t*)sm;
    float* s_pool        = (float*)(sm + SMEM_POOL_OFF);

    int blk = blockIdx.x;
    int yp = blk % 28; int frame = blk / 28;
    int t = frame % TT; int b = frame / TT;
    int tid = threadIdx.x;
    int w = tid >> 5; int lane = tid & 31;
    int g = lane >> 2; int q = lane & 3;
    int wm = w & 3;    int nh = w >> 2;

    for (int i = tid; i < 576; i += 256) s_pool[i] = 0.f;

    int rowbase = 8*yp - 3;
    for (int r = w; r < 99; r += 8) {
        int pIdx = r / 11, iy = r % 11;
        int tin = t + pIdx/3 - 1; int c = pIdx % 3;
        int grow = rowbase + iy;
        bool rv = (tin >= 0) && (tin < TT) && (grow >= 0) && (grow < HW);
        const float* src = rgb + (((size_t)(b*TT + tin)*3 + c)*HW + grow)*HW;
        uint32_t* dst = (uint32_t*)sm + (pIdx*11 + iy)*SIN_U32ROW;
        #pragma unroll
        for (int it = 0; it < 4; it++) {
            int x2 = lane + it*32;
            if (x2 < 114) {
                int c0 = 2*x2 - 3, c1 = c0 + 1;
                float v0 = (rv && c0 >= 0 && c0 < HW) ? src[c0] : 0.f;
                float v1 = (rv && c1 >= 0 && c1 < HW) ? src[c1] : 0.f;
                __nv_bfloat162 pk = __floats2bfloat162_rn(v0, v1);
                dst[x2] = *(uint32_t*)&pk;
            }
        }
    }
    __syncthreads();

    int x_lo = wm*16 + g;
    int x_hi = x_lo + 8; if (x_hi > 55) x_hi = 55;
    int blo = 2*x_lo + q;
    int bhi = 2*x_hi + q;

    float acc[2][4][4];
    #pragma unroll
    for (int y = 0; y < 2; y++)
        #pragma unroll
        for (int nt = 0; nt < 4; nt++)
            #pragma unroll
            for (int e = 0; e < 4; e++) acc[y][nt][e] = 0.f;

    const uint4* btab = g_wBv + nh*64 + lane;

    #pragma unroll
    for (int kt2 = 0; kt2 < 32; kt2++) {
        const int s0 = 2*kt2, s1 = s0 + 1;
        const int p0 = s0 / 7, ky0 = s0 - 7*p0;
        const int p1 = s1 / 7, ky1 = s1 - 7*p1;
        const int o0 = (p0*11 + ky0)*SIN_U32ROW;
        const int o1 = (s1 == 63) ? o0 : (p1*11 + ky1)*SIN_U32ROW;

        uint4 B0 = __ldg(btab + kt2*128);
        uint4 B1 = __ldg(btab + kt2*128 + 32);

        uint32_t a0[4], a1[4];
        a0[0] = in32[o0 + blo];        a0[1] = in32[o0 + bhi];
        a0[2] = in32[o1 + blo];        a0[3] = in32[o1 + bhi];
        a1[0] = in32[o0 + 464 + blo];  a1[1] = in32[o0 + 464 + bhi];
        a1[2] = in32[o1 + 464 + blo];  a1[3] = in32[o1 + 464 + bhi];

        mma16816(acc[0][0], a0, B0.x, B0.y);  mma16816(acc[1][0], a1, B0.x, B0.y);
        mma16816(acc[0][1], a0, B0.z, B0.w);  mma16816(acc[1][1], a1, B0.z, B0.w);
        mma16816(acc[0][2], a0, B1.x, B1.y);  mma16816(acc[1][2], a1, B1.x, B1.y);
        mma16816(acc[0][3], a0, B1.z, B1.w);  mma16816(acc[1][3], a1, B1.z, B1.w);
    }

    // ---- epilogue: bias + exact GELU + pool bins (floor 18/19/19) ----
    const float i18 = 1.f/18.f, i19 = 1.f/19.f;
    const int rowg0 = 2*yp, rowg1 = 2*yp + 1;
    const float rw0 = (rowg0 < 18) ? i18 : i19;
    const float rw1 = (rowg1 < 18) ? i18 : i19;
    const int roff0 = (rowg0 < 18) ? 0 : ((rowg0 < 37) ? 3 : 6);
    const int roff1 = (rowg1 < 18) ? 0 : ((rowg1 < 37) ? 3 : 6);
    const bool ymerge = (roff0 == roff1);

    const int x0 = wm*16 + g;
    const int x1 = x0 + 8;
    const bool v1 = (x1 < 56);
    const int xb0 = (x0 < 18) ? 0 : ((x0 < 37) ? 1 : 2);
    const int xb1 = (x1 < 18) ? 0 : ((x1 < 37) ? 1 : 2);
    const float cw0 = (x0 < 18) ? i18 : i19;
    const float cw1 = (x1 < 18) ? i18 : i19;
    const bool xmerge = v1 && (xb0 == xb1);

    #pragma unroll
    for (int nt = 0; nt < 4; nt++) {
        int ch0 = (nh*4 + nt)*8 + q*2;
        #pragma unroll
        for (int e = 0; e < 2; e++) {
            float bv = __ldg(g_biasf + ch0 + e);
            float g00 = gelu_exact(acc[0][nt][e] + bv);
            float g10 = gelu_exact(acc[1][nt][e] + bv);
            float* base = &s_pool[(ch0 + e)*9];
            if (v1) {
                float g01 = gelu_exact(acc[0][nt][2 + e] + bv);
                float g11 = gelu_exact(acc[1][nt][2 + e] + bv);
                if (ymerge) {
                    if (xmerge) {
                        atomicAdd(base + roff0 + xb0,
                                  ((g00 + g01)*rw0 + (g10 + g11)*rw1)*cw0);
                    } else {
                        atomicAdd(base + roff0 + xb0, (g00*rw0 + g10*rw1)*cw0);
                        atomicAdd(base + roff0 + xb1, (g01*rw0 + g11*rw1)*cw1);
                    }
                } else {
                    atomicAdd(base + roff0 + xb0, g00*rw0*cw0);
                    atomicAdd(base + roff1 + xb0, g10*rw1*cw0);
                    atomicAdd(base + roff0 + xb1, g01*rw0*cw1);
                    atomicAdd(base + roff1 + xb1, g11*rw1*cw1);
                }
            } else {
                if (ymerge) {
                    atomicAdd(base + roff0 + xb0, (g00*rw0 + g10*rw1)*cw0);
                } else {
                    atomicAdd(base + roff0 + xb0, g00*rw0*cw0);
                    atomicAdd(base + roff1 + xb0, g10*rw1*cw0);
                }
            }
        }
    }
    __syncthreads();
    int base = frame*576;
    for (int i = tid; i < 576; i += 256) atomicAdd(&g_pooled[base + i], s_pool[i]);
}

// ================= Mamba chain =================
// proj+in_proj batched over 2 positions per block (180 blocks > 148 SMs)
__global__ void proj_inproj_kernel(const float* __restrict__ proj_w,
                                   const float* __restrict__ proj_b,
                                   const float* __restrict__ in_w)
{
    __shared__ __align__(16) float s_p[2][576];
    __shared__ __align__(16) float s_x[2][128];
    int pos0 = blockIdx.x * 2;
    int tid = threadIdx.x;           // 256
    int w = tid >> 5, lane = tid & 31;
    for (int i = tid; i < 2*576; i += 256)
        ((float*)s_p)[i] = g_pooled[pos0*576 + i];
    __syncthreads();

    // phase 1: 128 rows of proj (K=576), each row dotted with 2 positions
    #pragma unroll
    for (int rr = 0; rr < 16; rr++) {
        int row = w*16 + rr;
        const float4* w4 = (const float4*)(proj_w + row*576);
        float a0 = 0.f, a1 = 0.f;
        #pragma unroll
        for (int i = 0; i < 4; i++) {
            float4 wv = __ldg(w4 + lane + 32*i);
            const float4 x0 = ((const float4*)s_p[0])[lane + 32*i];
            const float4 x1 = ((const float4*)s_p[1])[lane + 32*i];
            a0 += wv.x*x0.x + wv.y*x0.y + wv.z*x0.z + wv.w*x0.w;
            a1 += wv.x*x1.x + wv.y*x1.y + wv.z*x1.z + wv.w*x1.w;
        }
        if (lane < 16) {
            float4 wv = __ldg(w4 + 128 + lane);
            const float4 x0 = ((const float4*)s_p[0])[128 + lane];
            const float4 x1 = ((const float4*)s_p[1])[128 + lane];
            a0 += wv.x*x0.x + wv.y*x0.y + wv.z*x0.z + wv.w*x0.w;
            a1 += wv.x*x1.x + wv.y*x1.y + wv.z*x1.z + wv.w*x1.w;
        }
        #pragma unroll
        for (int o = 16; o > 0; o >>= 1) {
            a0 += __shfl_xor_sync(0xffffffffu, a0, o);
            a1 += __shfl_xor_sync(0xffffffffu, a1, o);
        }
        if (lane == 0) {
            float pb = __ldg(proj_b + row);
            s_x[0][row] = a0 + pb;
            s_x[1][row] = a1 + pb;
        }
    }
    __syncthreads();

    // phase 2: 512 rows of in_proj (K=128 = 1 float4/lane), 2 positions each
    #pragma unroll
    for (int rr = 0; rr < 64; rr++) {
        int row = w*64 + rr;
        float4 wv = __ldg((const float4*)(in_w + row*128) + lane);
        float4 x0 = ((const float4*)s_x[0])[lane];
        float4 x1 = ((const float4*)s_x[1])[lane];
        float a0 = wv.x*x0.x + wv.y*x0.y + wv.z*x0.z + wv.w*x0.w;
        float a1 = wv.x*x1.x + wv.y*x1.y + wv.z*x1.z + wv.w*x1.w;
        #pragma unroll
        for (int o = 16; o > 0; o >>= 1) {
            a0 += __shfl_xor_sync(0xffffffffu, a0, o);
            a1 += __shfl_xor_sync(0xffffffffu, a1, o);
        }
        if (lane == 0) {
            if (row < 256) {
                g_xm[pos0*256 + row]       = a0;
                g_xm[(pos0 + 1)*256 + row] = a1;
            } else {
                g_res[pos0*256 + (row - 256)]       = a0;
                g_res[(pos0 + 1)*256 + (row - 256)] = a1;
            }
        }
    }
}

__global__ void conv1d_xproj_kernel(const float* __restrict__ cw,
                                    const float* __restrict__ cb,
                                    const float* __restrict__ xw,
                                    const float* __restrict__ dtw,
                                    const float* __restrict__ dtb)
{
    __shared__ __align__(16) float s_u[256];
    __shared__ float s_xd[40];
    int pos = blockIdx.x; int b = pos / TT; int l = pos % TT;
    int d = threadIdx.x;             // 256
    int w = d >> 5, lane = d & 31;

    float xc = cb[d];
    #pragma unroll
    for (int k = 0; k < 4; k++) {
        int li = l - 3 + k;
        if (li >= 0) xc = fmaf(g_xm[(b*TT + li)*256 + d], cw[d*4 + k], xc);
    }
    float u = xc / (1.f + expf(-xc));
    s_u[d] = u;
    g_u[pos*256 + d] = u;
    __syncthreads();

    #pragma unroll
    for (int rr = 0; rr < 5; rr++) {
        int row = w*5 + rr;
        float4 w0 = __ldg((const float4*)(xw + row*256) + lane);
        float4 w1 = __ldg((const float4*)(xw + row*256) + 32 + lane);
        float4 x0 = *((const float4*)s_u + lane);
        float4 x1 = *((const float4*)s_u + 32 + lane);
        float a = w0.x*x0.x + w0.y*x0.y + w0.z*x0.z + w0.w*x0.w
                + w1.x*x1.x + w1.y*x1.y + w1.z*x1.z + w1.w*x1.w;
        #pragma unroll
        for (int o = 16; o > 0; o >>= 1) a += __shfl_xor_sync(0xffffffffu, a, o);
        if (lane == 0) s_xd[row] = a;
    }
    __syncthreads();

    float dr = dtb[d];
    #pragma unroll
    for (int k = 0; k < 8; k++) dr = fmaf(dtw[d*8 + k], s_xd[k], dr);
    float delta = (dr > 20.f) ? dr : log1pf(expf(dr));
    g_delta[pos*256 + d] = delta;
    if (d < 32) g_BC[pos*32 + d] = s_xd[8 + d];
}

// scan: thread = (b, d, n-quad). 4096 threads = 128 blocks x 32 (1 warp/SM
// on 128 SMs). h recurrences independent across n; y reduced over quad.
__global__ void scan_kernel(const float* __restrict__ Dp)
{
    int gidx = blockIdx.x * 32 + threadIdx.x;
    int b  = gidx >> 10;
    int rem = gidx & 1023;
    int d  = rem >> 2;
    int ng = rem & 3;

    float A[4], h[4];
    {
        float4 v = __ldg((const float4*)(g_negA + d*16) + ng);
        A[0] = v.x; A[1] = v.y; A[2] = v.z; A[3] = v.w;
    }
    #pragma unroll
    for (int n = 0; n < 4; n++) h[n] = 0.f;
    float Dd = __ldg(Dp + d);

    for (int l = 0; l < TT; l++) {
        int pos = b*TT + l;
        float delta = g_delta[pos*256 + d];
        float u     = g_u[pos*256 + d];
        const float4* BC4 = (const float4*)(g_BC + pos*32);
        float4 Bv = __ldg(BC4 + ng);
        float4 Cv = __ldg(BC4 + 4 + ng);
        float du = delta * u;
        const float* Bf = (const float*)&Bv;
        const float* Cf = (const float*)&Cv;
        float y = 0.f;
        #pragma unroll
        for (int n = 0; n < 4; n++) {
            float dA = expf(delta * A[n]);
            h[n] = fmaf(dA, h[n], du * Bf[n]);
            y = fmaf(h[n], Cf[n], y);
        }
        y += __shfl_xor_sync(0xffffffffu, y, 1);
        y += __shfl_xor_sync(0xffffffffu, y, 2);
        if (ng == 0) {
            float res = g_res[pos*256 + d];
            y = fmaf(u, Dd, y);
            y *= res / (1.f + expf(-res));
            g_y[pos*256 + d] = y;
        }
    }
}

// out projection batched over 2 positions per block (180 blocks)
__global__ void outproj_kernel(const float* __restrict__ ow,
                               float* __restrict__ out)
{
    __shared__ __align__(16) float s_y[2][256];
    int pos0 = blockIdx.x * 2;
    int tid = threadIdx.x;           // 256
    int w = tid >> 5, lane = tid & 31;
    s_y[0][tid] = g_y[pos0*256 + tid];
    s_y[1][tid] = g_y[(pos0 + 1)*256 + tid];
    __syncthreads();
    #pragma unroll
    for (int rr = 0; rr < 16; rr++) {
        int row = w*16 + rr;
        float4 w0 = __ldg((const float4*)(ow + row*256) + lane);
        float4 w1 = __ldg((const float4*)(ow + row*256) + 32 + lane);
        float a0, a1;
        {
            float4 y0 = ((const float4*)s_y[0])[lane];
            float4 y1 = ((const float4*)s_y[0])[32 + lane];
            a0 = w0.x*y0.x + w0.y*y0.y + w0.z*y0.z + w0.w*y0.w
               + w1.x*y1.x + w1.y*y1.y + w1.z*y1.z + w1.w*y1.w;
        }
        {
            float4 y0 = ((const float4*)s_y[1])[lane];
            float4 y1 = ((const float4*)s_y[1])[32 + lane];
            a1 = w0.x*y0.x + w0.y*y0.y + w0.z*y0.z + w0.w*y0.w
               + w1.x*y1.x + w1.y*y1.y + w1.z*y1.z + w1.w*y1.w;
        }
        #pragma unroll
        for (int o = 16; o > 0; o >>= 1) {
            a0 += __shfl_xor_sync(0xffffffffu, a0, o);
            a1 += __shfl_xor_sync(0xffffffffu, a1, o);
        }
        if (lane == 0) {
            out[pos0*128 + row]       = a0;
            out[(pos0 + 1)*128 + row] = a1;
        }
    }
}

// ============================================================
extern "C" void kernel_launch(void* const* d_in, const int* in_sizes, int n_in,
                              void* d_out, int out_size)
{
    (void)in_sizes; (void)n_in; (void)out_size;
    const float* rgb     = (const float*)d_in[0];
    const float* conv_w  = (const float*)d_in[1];
    const float* conv_b  = (const float*)d_in[2];
    const float* bn_g    = (const float*)d_in[3];
    const float* bn_b    = (const float*)d_in[4];
    const float* bn_m    = (const float*)d_in[5];
    const float* bn_v    = (const float*)d_in[6];
    const float* proj_w  = (const float*)d_in[7];
    const float* proj_b  = (const float*)d_in[8];
    const float* m_in_w  = (const float*)d_in[9];
    const float* m_cw    = (const float*)d_in[10];
    const float* m_cb    = (const float*)d_in[11];
    const float* m_xw    = (const float*)d_in[12];
    const float* m_dtw   = (const float*)d_in[13];
    const float* m_dtb   = (const float*)d_in[14];
    const float* m_Alog  = (const float*)d_in[15];
    const float* m_D     = (const float*)d_in[16];
    const float* m_ow    = (const float*)d_in[17];
    float* out = (float*)d_out;

    cudaFuncSetAttribute(conv_mma_kernel,
                         cudaFuncAttributeMaxDynamicSharedMemorySize, CONV_SMEM);

    // wfold + 2 zeros position conv at ncu launch index 5
    wfold_kernel<<<(32*4*32 + 255)/256, 256>>>(conv_w, conv_b, bn_g, bn_b,
                                               bn_m, bn_v, m_Alog);
    const int H = (FR*576) / 2;
    zero_pooled_kernel<<<(H + 255)/256, 256>>>(0);
    zero_pooled_kernel<<<(H + 255)/256, 256>>>(H);

    conv_mma_kernel<<<FR*28, 256, CONV_SMEM>>>(rgb);

    proj_inproj_kernel<<<FR/2, 256>>>(proj_w, proj_b, m_in_w);
    conv1d_xproj_kernel<<<FR, 256>>>(m_cw, m_cb, m_xw, m_dtw, m_dtb);
    scan_kernel<<<128, 32>>>(m_D);
    outproj_kernel<<<FR/2, 256>>>(m_ow, out);
}